// round 4
// baseline (speedup 1.0000x reference)
#include <cuda_runtime.h>
#include <math.h>
#include <stdint.h>

#define BB 16
#define NN 768
#define EE 1024
#define HH 16
#define DD 64
// mask addend in log2 domain: -1e16 * log2(e)
#define NEGV2 (-1.4426950e16f)

// Scratch (static device globals; no runtime allocation allowed).
// All values stored here are tf32-rounded (valid tf32 bit patterns in fp32).
__device__ float g_qh[BB * HH * NN * DD];   // (B,H,N,D), pre-scaled by log2e/32
__device__ float g_kh[BB * HH * NN * DD];
__device__ float g_vh[BB * HH * NN * DD];
__device__ float g_attn[BB * NN * EE];      // (B,N,E) pre-final-projection
__device__ float g_wtf[EE * EE];            // tf32-rounded Wf

// ---------------------------------------------------------------------------
// helpers
// ---------------------------------------------------------------------------
__device__ __forceinline__ uint32_t f2tf(float x) {
    uint32_t r;
    asm("cvt.rna.tf32.f32 %0, %1;" : "=r"(r) : "f"(x));
    return r;
}
__device__ __forceinline__ float f2tf_f(float x) {
    return __uint_as_float(f2tf(x));
}
__device__ __forceinline__ float ex2(float x) {
    float y;
    asm("ex2.approx.f32 %0, %1;" : "=f"(y) : "f"(x));
    return y;
}
__device__ __forceinline__ void mma_tf32(float d[4],
                                         uint32_t a0, uint32_t a1, uint32_t a2, uint32_t a3,
                                         uint32_t b0, uint32_t b1) {
    asm volatile(
        "mma.sync.aligned.m16n8k8.row.col.f32.tf32.tf32.f32 "
        "{%0,%1,%2,%3}, {%4,%5,%6,%7}, {%8,%9}, {%0,%1,%2,%3};\n"
        : "+f"(d[0]), "+f"(d[1]), "+f"(d[2]), "+f"(d[3])
        : "r"(a0), "r"(a1), "r"(a2), "r"(a3), "r"(b0), "r"(b1));
}
__device__ __forceinline__ void cp16(void* smem, const void* gmem) {
    uint32_t s = (uint32_t)__cvta_generic_to_shared(smem);
    asm volatile("cp.async.cg.shared.global [%0], [%1], 16;\n" :: "r"(s), "l"(gmem));
}
__device__ __forceinline__ void cp_commit() { asm volatile("cp.async.commit_group;\n"); }
__device__ __forceinline__ void cp_wait0() { asm volatile("cp.async.wait_group 0;\n"); }

__device__ __forceinline__ void f4arr(float4 v, float* a) {
    a[0] = v.x; a[1] = v.y; a[2] = v.z; a[3] = v.w;
}

// ---------------------------------------------------------------------------
// Stage A: per-head projections (fp32 math, tf32-rounded output).
// Q additionally scaled by log2e/sqrt(E) so softmax can use raw ex2.
// ---------------------------------------------------------------------------
__global__ __launch_bounds__(256) void proj_kernel(
    const float* __restrict__ q, const float* __restrict__ k, const float* __restrict__ v,
    const float* __restrict__ Wq, const float* __restrict__ Wk, const float* __restrict__ Wv)
{
    __shared__ float Xs[64][68];
    __shared__ float Wt[64][68];

    const int which = blockIdx.z;
    const float* X = (which == 0) ? q : (which == 1) ? k : v;
    const float* W = (which == 0) ? Wq : (which == 1) ? Wk : Wv;
    float* Y = (which == 0) ? g_qh : (which == 1) ? g_kh : g_vh;
    const float oscl = (which == 0) ? (0.03125f * 1.44269504f) : 1.0f;

    const int bh = blockIdx.y;
    const int b = bh >> 4, h = bh & 15;
    const int n0 = blockIdx.x * 64;
    const int tid = threadIdx.x;

    {
        const int rr0 = tid >> 4;
        const int c4 = (tid & 15) * 4;
        const float* src = X + ((size_t)b * NN) * EE + h * DD;
        #pragma unroll
        for (int rr = 0; rr < 64; rr += 16) {
            float4 val = *(const float4*)(src + (size_t)(n0 + rr0 + rr) * EE + c4);
            *(float4*)&Xs[rr0 + rr][c4] = val;
        }
    }
    {
        const int e0t = tid & 15;
        const int dq = (tid >> 4) * 4;
        const float* wsrc = W + h * DD * DD;
        #pragma unroll
        for (int ee = 0; ee < 64; ee += 16) {
            const int e = e0t + ee;
            float4 wv = *(const float4*)(wsrc + e * DD + dq);
            Wt[dq + 0][e] = wv.x; Wt[dq + 1][e] = wv.y;
            Wt[dq + 2][e] = wv.z; Wt[dq + 3][e] = wv.w;
        }
    }
    __syncthreads();

    const int ty = tid >> 4, tx = tid & 15;
    const int r = ty * 4, c = tx * 4;
    float acc[4][4] = {};

    #pragma unroll
    for (int d4 = 0; d4 < 64; d4 += 4) {
        float xa[4][4], wa[4][4];
        #pragma unroll
        for (int i = 0; i < 4; i++) f4arr(*(const float4*)&Xs[r + i][d4], xa[i]);
        #pragma unroll
        for (int t = 0; t < 4; t++) f4arr(*(const float4*)&Wt[d4 + t][c], wa[t]);
        #pragma unroll
        for (int i = 0; i < 4; i++)
            #pragma unroll
            for (int t = 0; t < 4; t++)
                #pragma unroll
                for (int j = 0; j < 4; j++)
                    acc[i][j] += xa[i][t] * wa[t][j];
    }

    float* dst = Y + (((size_t)bh) * NN + n0 + r) * DD + c;
    #pragma unroll
    for (int i = 0; i < 4; i++) {
        *(float4*)(dst + (size_t)i * DD) =
            make_float4(f2tf_f(acc[i][0] * oscl), f2tf_f(acc[i][1] * oscl),
                        f2tf_f(acc[i][2] * oscl), f2tf_f(acc[i][3] * oscl));
    }
}

// ---------------------------------------------------------------------------
// Wf -> tf32 prepass
// ---------------------------------------------------------------------------
__global__ __launch_bounds__(256) void cvtW_kernel(const float* __restrict__ Wf)
{
    int i = (blockIdx.x * 256 + threadIdx.x) * 4;
    float4 v = *(const float4*)(Wf + i);
    *(float4*)(g_wtf + i) = make_float4(f2tf_f(v.x), f2tf_f(v.y), f2tf_f(v.z), f2tf_f(v.w));
}

// ---------------------------------------------------------------------------
// Stage B: flash attention, tf32 mma, ktile=32 double-buffered cp.async.
// grid (6, 256), block 256, dynamic smem 79872 B, 2 CTAs/SM.
// smem (floats): Qs[128][76] | Ks[2][32][76] | Vs[2][32][72] | madd[768]
// ---------------------------------------------------------------------------
#define QS(r, c_)      sm[(r) * 76 + (c_)]
#define KS(bf, r, c_)  sm[9728 + (bf) * 2432 + (r) * 76 + (c_)]
#define VS(bf, r, c_)  sm[14592 + (bf) * 2304 + (r) * 72 + (c_)]
#define MADD(i)        sm[19200 + (i)]

__global__ __launch_bounds__(256, 2) void attn_tf32_kernel(const float* __restrict__ mask)
{
    extern __shared__ float sm[];

    const int bh = blockIdx.y;
    const int b = bh >> 4, h = bh & 15;
    const int q0 = blockIdx.x * 128;
    const int tid = threadIdx.x;
    const int w = tid >> 5;
    const int lane = tid & 31;
    const int g = lane >> 2;
    const int qd = lane & 3;

    const float* kb = g_kh + ((size_t)bh * NN) * DD;
    const float* vb = g_vh + ((size_t)bh * NN) * DD;

    // additive mask row for this head (log2-domain)
    for (int i = tid; i < NN; i += 256)
        MADD(i) = (mask[h * NN + i] == -INFINITY) ? NEGV2 : 0.f;

    // stage Q tile (already tf32 + scaled)
    const float* qb = g_qh + ((size_t)bh * NN + q0) * DD;
    {
        const int rr = tid >> 4, c4 = (tid & 15) * 4;
        #pragma unroll
        for (int i = 0; i < 8; i++)
            *(float4*)&QS(rr + 16 * i, c4) =
                *(const float4*)(qb + (size_t)(rr + 16 * i) * DD + c4);
    }

    const int qrow = 16 * w + g;
    const float addq0 = (mask[h * NN + q0 + qrow] == -INFINITY) ? NEGV2 : 0.f;
    const float addq1 = (mask[h * NN + q0 + qrow + 8] == -INFINITY) ? NEGV2 : 0.f;

    float m0r = -INFINITY, m1r = -INFINITY, l0 = 0.f, l1 = 0.f;
    float o[8][4] = {};

    const int shbase = lane & ~3;
    const int s0l = shbase + (qd >> 1);
    const int s2l = shbase + (qd >> 1) + 2;
    const bool odd = qd & 1;

    // cp.async mapping: row = tid>>3 (0..31), col8 = (tid&7)*8
    const int crow = tid >> 3;
    const int ccol = (tid & 7) * 8;

    // prologue: stage tile 0 into buf 0
    {
        const float* ks = kb + (size_t)crow * DD + ccol;
        const float* vs = vb + (size_t)crow * DD + ccol;
        cp16(&KS(0, crow, ccol),     ks);
        cp16(&KS(0, crow, ccol + 4), ks + 4);
        cp16(&VS(0, crow, ccol),     vs);
        cp16(&VS(0, crow, ccol + 4), vs + 4);
    }
    cp_commit();

    for (int t = 0; t < NN / 32; t++) {
        const int buf = t & 1;
        cp_wait0();
        __syncthreads();     // tile t visible to all; prior reads of buf^1 done

        if (t + 1 < NN / 32) {
            const float* ks = kb + (size_t)((t + 1) * 32 + crow) * DD + ccol;
            const float* vs = vb + (size_t)((t + 1) * 32 + crow) * DD + ccol;
            cp16(&KS(buf ^ 1, crow, ccol),     ks);
            cp16(&KS(buf ^ 1, crow, ccol + 4), ks + 4);
            cp16(&VS(buf ^ 1, crow, ccol),     vs);
            cp16(&VS(buf ^ 1, crow, ccol + 4), vs + 4);
            cp_commit();
        }

        // S = Q K^T over 32 cols
        float s[4][4] = {};
        #pragma unroll
        for (int kk = 0; kk < 8; kk++) {
            uint32_t a0 = __float_as_uint(QS(qrow,     kk * 8 + qd));
            uint32_t a1 = __float_as_uint(QS(qrow + 8, kk * 8 + qd));
            uint32_t a2 = __float_as_uint(QS(qrow,     kk * 8 + qd + 4));
            uint32_t a3 = __float_as_uint(QS(qrow + 8, kk * 8 + qd + 4));
            #pragma unroll
            for (int nt = 0; nt < 4; nt++) {
                uint32_t b0 = __float_as_uint(KS(buf, nt * 8 + g, kk * 8 + qd));
                uint32_t b1 = __float_as_uint(KS(buf, nt * 8 + g, kk * 8 + qd + 4));
                mma_tf32(s[nt], a0, a1, a2, a3, b0, b1);
            }
        }

        // mask + online softmax (log2 domain)
        const int kt = t * 32;
        float pm0 = -INFINITY, pm1 = -INFINITY;
        #pragma unroll
        for (int nt = 0; nt < 4; nt++) {
            float2 mk = *(const float2*)&MADD(kt + nt * 8 + 2 * qd);
            s[nt][0] += fmaxf(addq0 + mk.x, NEGV2);
            s[nt][1] += fmaxf(addq0 + mk.y, NEGV2);
            s[nt][2] += fmaxf(addq1 + mk.x, NEGV2);
            s[nt][3] += fmaxf(addq1 + mk.y, NEGV2);
            pm0 = fmaxf(pm0, fmaxf(s[nt][0], s[nt][1]));
            pm1 = fmaxf(pm1, fmaxf(s[nt][2], s[nt][3]));
        }
        pm0 = fmaxf(pm0, __shfl_xor_sync(0xffffffffu, pm0, 1));
        pm0 = fmaxf(pm0, __shfl_xor_sync(0xffffffffu, pm0, 2));
        pm1 = fmaxf(pm1, __shfl_xor_sync(0xffffffffu, pm1, 1));
        pm1 = fmaxf(pm1, __shfl_xor_sync(0xffffffffu, pm1, 2));

        const float mn0 = fmaxf(m0r, pm0), mn1 = fmaxf(m1r, pm1);
        const float corr0 = ex2(m0r - mn0), corr1 = ex2(m1r - mn1);
        m0r = mn0; m1r = mn1;

        float rs0 = 0.f, rs1 = 0.f;
        #pragma unroll
        for (int nt = 0; nt < 4; nt++) {
            s[nt][0] = ex2(s[nt][0] - mn0); rs0 += s[nt][0];
            s[nt][1] = ex2(s[nt][1] - mn0); rs0 += s[nt][1];
            s[nt][2] = ex2(s[nt][2] - mn1); rs1 += s[nt][2];
            s[nt][3] = ex2(s[nt][3] - mn1); rs1 += s[nt][3];
        }
        rs0 += __shfl_xor_sync(0xffffffffu, rs0, 1);
        rs0 += __shfl_xor_sync(0xffffffffu, rs0, 2);
        rs1 += __shfl_xor_sync(0xffffffffu, rs1, 1);
        rs1 += __shfl_xor_sync(0xffffffffu, rs1, 2);
        l0 = l0 * corr0 + rs0;
        l1 = l1 * corr1 + rs1;

        #pragma unroll
        for (int dt = 0; dt < 8; dt++) {
            o[dt][0] *= corr0; o[dt][1] *= corr0;
            o[dt][2] *= corr1; o[dt][3] *= corr1;
        }

        // O += P V  (C-fragment -> A-fragment via quad shuffles)
        #pragma unroll
        for (int kk = 0; kk < 4; kk++) {
            float e0 = __shfl_sync(0xffffffffu, s[kk][0], s0l);
            float e1 = __shfl_sync(0xffffffffu, s[kk][1], s0l);
            float e2 = __shfl_sync(0xffffffffu, s[kk][2], s0l);
            float e3 = __shfl_sync(0xffffffffu, s[kk][3], s0l);
            float f0 = __shfl_sync(0xffffffffu, s[kk][0], s2l);
            float f1 = __shfl_sync(0xffffffffu, s[kk][1], s2l);
            float f2 = __shfl_sync(0xffffffffu, s[kk][2], s2l);
            float f3 = __shfl_sync(0xffffffffu, s[kk][3], s2l);
            uint32_t a0 = f2tf(odd ? e1 : e0);
            uint32_t a1 = f2tf(odd ? e3 : e2);
            uint32_t a2 = f2tf(odd ? f1 : f0);
            uint32_t a3 = f2tf(odd ? f3 : f2);
            #pragma unroll
            for (int dt = 0; dt < 8; dt++) {
                uint32_t b0 = __float_as_uint(VS(buf, kk * 8 + qd,     dt * 8 + g));
                uint32_t b1 = __float_as_uint(VS(buf, kk * 8 + qd + 4, dt * 8 + g));
                mma_tf32(o[dt], a0, a1, a2, a3, b0, b1);
            }
        }
    }

    // epilogue: normalize, tf32-round, write (B,N,E)
    const float inv0 = 1.f / l0, inv1 = 1.f / l1;
    float* ob = g_attn + ((size_t)b * NN + q0 + 16 * w) * EE + h * DD;
    #pragma unroll
    for (int dt = 0; dt < 8; dt++) {
        float2 v0 = make_float2(f2tf_f(o[dt][0] * inv0), f2tf_f(o[dt][1] * inv0));
        float2 v1 = make_float2(f2tf_f(o[dt][2] * inv1), f2tf_f(o[dt][3] * inv1));
        *(float2*)(ob + (size_t)g * EE + dt * 8 + 2 * qd) = v0;
        *(float2*)(ob + (size_t)(g + 8) * EE + dt * 8 + 2 * qd) = v1;
    }
}

// ---------------------------------------------------------------------------
// Stage C: out = g_attn @ Wf^T, tf32 mma. 128x128x32, 2-stage single-barrier
// cp.async pipeline. grid (8, 96), block 256, dynamic smem 73728 B.
// smem: As[2][128][36] | Ws[2][128][36]
// ---------------------------------------------------------------------------
#define GAS(bf, r, c_) sm[(bf) * 4608 + (r) * 36 + (c_)]
#define GWS(bf, r, c_) sm[9216 + (bf) * 4608 + (r) * 36 + (c_)]

__global__ __launch_bounds__(256, 2) void gemm_tf32_kernel(float* __restrict__ out)
{
    extern __shared__ float sm[];

    const int e0 = blockIdx.x * 128;
    const int m0 = blockIdx.y * 128;
    const int tid = threadIdx.x;
    const int w = tid >> 5;
    const int lane = tid & 31;
    const int g = lane >> 2, qd = lane & 3;
    const int mb = (w & 1) * 64;
    const int nb = (w >> 1) * 32;

    const float* Ab = g_attn + (size_t)m0 * EE;
    const float* Wb = g_wtf + (size_t)e0 * EE;

    const int rr = tid >> 3;           // 0..31
    const int c4 = (tid & 7) * 4;      // 0..28

    float acc[4][4][4] = {};

    // prologue: stage chunk 0 into buf 0
    #pragma unroll
    for (int i = 0; i < 4; i++) {
        cp16(&GAS(0, rr + 32 * i, c4), Ab + (size_t)(rr + 32 * i) * EE + c4);
        cp16(&GWS(0, rr + 32 * i, c4), Wb + (size_t)(rr + 32 * i) * EE + c4);
    }
    cp_commit();

    for (int it = 0; it < EE / 32; it++) {
        const int buf = it & 1;
        cp_wait0();
        __syncthreads();   // chunk it visible; prior reads of buf^1 done

        if (it + 1 < EE / 32) {
            const int kc = (it + 1) * 32;
            #pragma unroll
            for (int i = 0; i < 4; i++) {
                cp16(&GAS(buf ^ 1, rr + 32 * i, c4),
                     Ab + (size_t)(rr + 32 * i) * EE + kc + c4);
                cp16(&GWS(buf ^ 1, rr + 32 * i, c4),
                     Wb + (size_t)(rr + 32 * i) * EE + kc + c4);
            }
            cp_commit();
        }

        #pragma unroll
        for (int kk = 0; kk < 4; kk++) {
            uint32_t a[4][4];
            #pragma unroll
            for (int mt = 0; mt < 4; mt++) {
                const int row = mb + mt * 16 + g;
                a[mt][0] = __float_as_uint(GAS(buf, row,     kk * 8 + qd));
                a[mt][1] = __float_as_uint(GAS(buf, row + 8, kk * 8 + qd));
                a[mt][2] = __float_as_uint(GAS(buf, row,     kk * 8 + qd + 4));
                a[mt][3] = __float_as_uint(GAS(buf, row + 8, kk * 8 + qd + 4));
            }
            #pragma unroll
            for (int nt = 0; nt < 4; nt++) {
                uint32_t b0 = __float_as_uint(GWS(buf, nb + nt * 8 + g, kk * 8 + qd));
                uint32_t b1 = __float_as_uint(GWS(buf, nb + nt * 8 + g, kk * 8 + qd + 4));
                #pragma unroll
                for (int mt = 0; mt < 4; mt++)
                    mma_tf32(acc[mt][nt], a[mt][0], a[mt][1], a[mt][2], a[mt][3], b0, b1);
            }
        }
    }

    #pragma unroll
    for (int mt = 0; mt < 4; mt++) {
        const int row0 = m0 + mb + mt * 16 + g;
        #pragma unroll
        for (int nt = 0; nt < 4; nt++) {
            const int col = e0 + nb + nt * 8 + 2 * qd;
            *(float2*)(out + (size_t)row0 * EE + col) =
                make_float2(acc[mt][nt][0], acc[mt][nt][1]);
            *(float2*)(out + (size_t)(row0 + 8) * EE + col) =
                make_float2(acc[mt][nt][2], acc[mt][nt][3]);
        }
    }
}

// ---------------------------------------------------------------------------
extern "C" void kernel_launch(void* const* d_in, const int* in_sizes, int n_in,
                              void* d_out, int out_size)
{
    const float* q    = (const float*)d_in[0];
    const float* k    = (const float*)d_in[1];
    const float* v    = (const float*)d_in[2];
    const float* mask = (const float*)d_in[3];
    const float* Wq   = (const float*)d_in[4];
    const float* Wk   = (const float*)d_in[5];
    const float* Wv   = (const float*)d_in[6];
    const float* Wf   = (const float*)d_in[7];
    float* out = (float*)d_out;

    const int attn_smem = 19968 * (int)sizeof(float);   // 79872
    const int gemm_smem = 18432 * (int)sizeof(float);   // 73728
    cudaFuncSetAttribute(attn_tf32_kernel,
                         cudaFuncAttributeMaxDynamicSharedMemorySize, attn_smem);
    cudaFuncSetAttribute(gemm_tf32_kernel,
                         cudaFuncAttributeMaxDynamicSharedMemorySize, gemm_smem);

    proj_kernel<<<dim3(NN / 64, BB * HH, 3), 256>>>(q, k, v, Wq, Wk, Wv);
    cvtW_kernel<<<EE * EE / 1024, 256>>>(Wf);
    attn_tf32_kernel<<<dim3(NN / 128, BB * HH), 256, attn_smem>>>(mask);
    gemm_tf32_kernel<<<dim3(EE / 128, (BB * NN) / 128), 256, gemm_smem>>>(out);
}

// round 7
// speedup vs baseline: 1.1812x; 1.1812x over previous
#include <cuda_runtime.h>
#include <math.h>
#include <stdint.h>

#define BB 16
#define NN 768
#define EE 1024
#define HH 16
#define DD 64
#define NEGV (-1e16f)

// Scratch (static device globals; no runtime allocation allowed).
// All values stored here are tf32-rounded (valid tf32 bit patterns in fp32).
__device__ float g_qh[BB * HH * NN * DD];   // (B,H,N,D), pre-scaled by 1/32
__device__ float g_kh[BB * HH * NN * DD];
__device__ float g_vh[BB * HH * NN * DD];
__device__ float g_attn[BB * NN * EE];      // (B,N,E) pre-final-projection
__device__ float g_wtf[EE * EE];            // tf32-rounded Wf

// ---------------------------------------------------------------------------
// helpers
// ---------------------------------------------------------------------------
__device__ __forceinline__ uint32_t f2tf(float x) {
    uint32_t r;
    asm("cvt.rna.tf32.f32 %0, %1;" : "=r"(r) : "f"(x));
    return r;
}
__device__ __forceinline__ float f2tf_f(float x) {
    return __uint_as_float(f2tf(x));
}
__device__ __forceinline__ void mma_tf32(float d[4],
                                         uint32_t a0, uint32_t a1, uint32_t a2, uint32_t a3,
                                         uint32_t b0, uint32_t b1) {
    asm volatile(
        "mma.sync.aligned.m16n8k8.row.col.f32.tf32.tf32.f32 "
        "{%0,%1,%2,%3}, {%4,%5,%6,%7}, {%8,%9}, {%0,%1,%2,%3};\n"
        : "+f"(d[0]), "+f"(d[1]), "+f"(d[2]), "+f"(d[3])
        : "r"(a0), "r"(a1), "r"(a2), "r"(a3), "r"(b0), "r"(b1));
}
__device__ __forceinline__ void cp16(void* smem, const void* gmem) {
    uint32_t s = (uint32_t)__cvta_generic_to_shared(smem);
    asm volatile("cp.async.cg.shared.global [%0], [%1], 16;\n" :: "r"(s), "l"(gmem));
}
__device__ __forceinline__ void cp_commit() { asm volatile("cp.async.commit_group;\n"); }
__device__ __forceinline__ void cp_wait0() { asm volatile("cp.async.wait_group 0;\n"); }

// ---------------------------------------------------------------------------
// Stage A (merged): per-head projections via legacy tf32 mma + Wf tf32 prepass.
// grid (6, 256, 4), block 256.
//   z = 0,1,2 : project q/k/v -> g_qh/g_kh/g_vh   (128 rows x 64 outs, K=64)
//   z = 3     : g_wtf = tf32(Wf)
// smem (floats): Xs[128][76] | Ws[64][76]  = 58368 B
// ---------------------------------------------------------------------------
#define PXS(r, c_) sm[(r) * 76 + (c_)]
#define PWS(r, c_) sm[9728 + (r) * 76 + (c_)]

__global__ __launch_bounds__(256) void proj_mma_kernel(
    const float* __restrict__ q, const float* __restrict__ k, const float* __restrict__ v,
    const float* __restrict__ Wq, const float* __restrict__ Wk, const float* __restrict__ Wv,
    const float* __restrict__ Wf)
{
    extern __shared__ float sm[];
    const int which = blockIdx.z;
    const int tid = threadIdx.x;

    if (which == 3) {
        // cvtW: 1536 blocks x 256 threads, one float4 each over 1024x1024
        const int idx4 = (blockIdx.y * 6 + blockIdx.x) * 256 + tid;
        if (idx4 < EE * EE / 4) {
            float4 vv = *(const float4*)(Wf + idx4 * 4);
            *(float4*)(g_wtf + idx4 * 4) =
                make_float4(f2tf_f(vv.x), f2tf_f(vv.y), f2tf_f(vv.z), f2tf_f(vv.w));
        }
        return;
    }

    const float* X = (which == 0) ? q : (which == 1) ? k : v;
    const float* W = (which == 0) ? Wq : (which == 1) ? Wk : Wv;
    float* Y = (which == 0) ? g_qh : (which == 1) ? g_kh : g_vh;
    const float oscl = (which == 0) ? 0.03125f : 1.0f;   // fold 1/sqrt(E) into Q

    const int bh = blockIdx.y;
    const int b = bh >> 4, h = bh & 15;
    const int n0 = blockIdx.x * 128;

    // stage X tile (128 x 64) and W (64 x 64), tf32-rounding each value
    {
        const int rr = tid >> 4;
        const int c4 = (tid & 15) * 4;
        const float* src = X + ((size_t)b * NN + n0) * EE + h * DD;
        #pragma unroll
        for (int i = 0; i < 8; i++) {
            const int row = rr + 16 * i;
            float4 vv = *(const float4*)(src + (size_t)row * EE + c4);
            *(float4*)&PXS(row, c4) =
                make_float4(f2tf_f(vv.x), f2tf_f(vv.y), f2tf_f(vv.z), f2tf_f(vv.w));
        }
        const float* wsrc = W + h * DD * DD;
        #pragma unroll
        for (int i = 0; i < 4; i++) {
            const int row = rr + 16 * i;
            float4 wv = *(const float4*)(wsrc + row * DD + c4);
            *(float4*)&PWS(row, c4) =
                make_float4(f2tf_f(wv.x), f2tf_f(wv.y), f2tf_f(wv.z), f2tf_f(wv.w));
        }
    }
    __syncthreads();

    const int w = tid >> 5;
    const int lane = tid & 31;
    const int g = lane >> 2;
    const int qd = lane & 3;
    const int qrow = 16 * w + g;

    float acc[8][4] = {};
    #pragma unroll
    for (int kk = 0; kk < 8; kk++) {
        uint32_t a0 = __float_as_uint(PXS(qrow,     kk * 8 + qd));
        uint32_t a1 = __float_as_uint(PXS(qrow + 8, kk * 8 + qd));
        uint32_t a2 = __float_as_uint(PXS(qrow,     kk * 8 + qd + 4));
        uint32_t a3 = __float_as_uint(PXS(qrow + 8, kk * 8 + qd + 4));
        #pragma unroll
        for (int nt = 0; nt < 8; nt++) {
            uint32_t b0 = __float_as_uint(PWS(nt * 8 + g, kk * 8 + qd));
            uint32_t b1 = __float_as_uint(PWS(nt * 8 + g, kk * 8 + qd + 4));
            mma_tf32(acc[nt], a0, a1, a2, a3, b0, b1);
        }
    }

    // epilogue: tf32-round, write (sector-complete float2 stores)
    float* dst = Y + (((size_t)bh) * NN + n0 + 16 * w) * DD;
    #pragma unroll
    for (int nt = 0; nt < 8; nt++) {
        const int col = nt * 8 + 2 * qd;
        *(float2*)(dst + (size_t)g * DD + col) =
            make_float2(f2tf_f(acc[nt][0] * oscl), f2tf_f(acc[nt][1] * oscl));
        *(float2*)(dst + (size_t)(g + 8) * DD + col) =
            make_float2(f2tf_f(acc[nt][2] * oscl), f2tf_f(acc[nt][3] * oscl));
    }
}

// ---------------------------------------------------------------------------
// Stage B: flash attention (R3 version: ktile=64, legacy tf32 mma).
// grid (6, 256), block 256, dynamic smem 79872 B.
// smem (floats): Qs[128][76] | Ks[64][76] | Vs[64][72] | madd[768]
// ---------------------------------------------------------------------------
#define QS(r, c_) sm[(r) * 76 + (c_)]
#define KS(r, c_) sm[9728 + (r) * 76 + (c_)]
#define VS(r, c_) sm[14592 + (r) * 72 + (c_)]
#define MADD(i)   sm[19200 + (i)]

__global__ __launch_bounds__(256, 2) void attn_tf32_kernel(const float* __restrict__ mask)
{
    extern __shared__ float sm[];

    const int bh = blockIdx.y;
    const int b = bh >> 4, h = bh & 15;
    const int q0 = blockIdx.x * 128;
    const int tid = threadIdx.x;
    const int w = tid >> 5;
    const int lane = tid & 31;
    const int g = lane >> 2;
    const int qd = lane & 3;

    for (int i = tid; i < NN; i += 256)
        MADD(i) = (mask[h * NN + i] == -INFINITY) ? NEGV : 0.f;

    const float* qb = g_qh + ((size_t)bh * NN + q0) * DD;
    {
        const int rr = tid >> 4, c4 = (tid & 15) * 4;
        #pragma unroll
        for (int i = 0; i < 8; i++)
            *(float4*)&QS(rr + 16 * i, c4) =
                *(const float4*)(qb + (size_t)(rr + 16 * i) * DD + c4);
    }
    __syncthreads();

    const int qrow = 16 * w + g;
    const float addq0 = MADD(q0 + qrow);
    const float addq1 = MADD(q0 + qrow + 8);

    float m0r = -INFINITY, m1r = -INFINITY, l0 = 0.f, l1 = 0.f;
    float o[8][4] = {};

    const float* kb = g_kh + ((size_t)bh * NN) * DD;
    const float* vb = g_vh + ((size_t)bh * NN) * DD;

    const int shbase = lane & ~3;
    const int s0l = shbase + (qd >> 1);
    const int s2l = shbase + (qd >> 1) + 2;
    const bool odd = qd & 1;

    for (int kt = 0; kt < NN; kt += 64) {
        __syncthreads();
        {
            const int rr = tid >> 4, c4 = (tid & 15) * 4;
            #pragma unroll
            for (int i = 0; i < 4; i++) {
                *(float4*)&KS(rr + 16 * i, c4) =
                    *(const float4*)(kb + (size_t)(kt + rr + 16 * i) * DD + c4);
                *(float4*)&VS(rr + 16 * i, c4) =
                    *(const float4*)(vb + (size_t)(kt + rr + 16 * i) * DD + c4);
            }
        }
        __syncthreads();

        float s[8][4] = {};
        #pragma unroll
        for (int kk = 0; kk < 8; kk++) {
            uint32_t a0 = __float_as_uint(QS(qrow,     kk * 8 + qd));
            uint32_t a1 = __float_as_uint(QS(qrow + 8, kk * 8 + qd));
            uint32_t a2 = __float_as_uint(QS(qrow,     kk * 8 + qd + 4));
            uint32_t a3 = __float_as_uint(QS(qrow + 8, kk * 8 + qd + 4));
            #pragma unroll
            for (int nt = 0; nt < 8; nt++) {
                uint32_t b0 = __float_as_uint(KS(nt * 8 + g, kk * 8 + qd));
                uint32_t b1 = __float_as_uint(KS(nt * 8 + g, kk * 8 + qd + 4));
                mma_tf32(s[nt], a0, a1, a2, a3, b0, b1);
            }
        }

        float pm0 = -INFINITY, pm1 = -INFINITY;
        #pragma unroll
        for (int nt = 0; nt < 8; nt++) {
            float2 mk = *(const float2*)&MADD(kt + nt * 8 + 2 * qd);
            s[nt][0] += fmaxf(addq0 + mk.x, NEGV);
            s[nt][1] += fmaxf(addq0 + mk.y, NEGV);
            s[nt][2] += fmaxf(addq1 + mk.x, NEGV);
            s[nt][3] += fmaxf(addq1 + mk.y, NEGV);
            pm0 = fmaxf(pm0, fmaxf(s[nt][0], s[nt][1]));
            pm1 = fmaxf(pm1, fmaxf(s[nt][2], s[nt][3]));
        }
        pm0 = fmaxf(pm0, __shfl_xor_sync(0xffffffffu, pm0, 1));
        pm0 = fmaxf(pm0, __shfl_xor_sync(0xffffffffu, pm0, 2));
        pm1 = fmaxf(pm1, __shfl_xor_sync(0xffffffffu, pm1, 1));
        pm1 = fmaxf(pm1, __shfl_xor_sync(0xffffffffu, pm1, 2));

        const float mn0 = fmaxf(m0r, pm0), mn1 = fmaxf(m1r, pm1);
        const float corr0 = __expf(m0r - mn0), corr1 = __expf(m1r - mn1);
        m0r = mn0; m1r = mn1;

        float rs0 = 0.f, rs1 = 0.f;
        #pragma unroll
        for (int nt = 0; nt < 8; nt++) {
            s[nt][0] = __expf(s[nt][0] - mn0); rs0 += s[nt][0];
            s[nt][1] = __expf(s[nt][1] - mn0); rs0 += s[nt][1];
            s[nt][2] = __expf(s[nt][2] - mn1); rs1 += s[nt][2];
            s[nt][3] = __expf(s[nt][3] - mn1); rs1 += s[nt][3];
        }
        rs0 += __shfl_xor_sync(0xffffffffu, rs0, 1);
        rs0 += __shfl_xor_sync(0xffffffffu, rs0, 2);
        rs1 += __shfl_xor_sync(0xffffffffu, rs1, 1);
        rs1 += __shfl_xor_sync(0xffffffffu, rs1, 2);
        l0 = l0 * corr0 + rs0;
        l1 = l1 * corr1 + rs1;

        #pragma unroll
        for (int dt = 0; dt < 8; dt++) {
            o[dt][0] *= corr0; o[dt][1] *= corr0;
            o[dt][2] *= corr1; o[dt][3] *= corr1;
        }

        #pragma unroll
        for (int kk = 0; kk < 8; kk++) {
            float e0 = __shfl_sync(0xffffffffu, s[kk][0], s0l);
            float e1 = __shfl_sync(0xffffffffu, s[kk][1], s0l);
            float e2 = __shfl_sync(0xffffffffu, s[kk][2], s0l);
            float e3 = __shfl_sync(0xffffffffu, s[kk][3], s0l);
            float f0 = __shfl_sync(0xffffffffu, s[kk][0], s2l);
            float f1 = __shfl_sync(0xffffffffu, s[kk][1], s2l);
            float f2 = __shfl_sync(0xffffffffu, s[kk][2], s2l);
            float f3 = __shfl_sync(0xffffffffu, s[kk][3], s2l);
            uint32_t a0 = f2tf(odd ? e1 : e0);
            uint32_t a1 = f2tf(odd ? e3 : e2);
            uint32_t a2 = f2tf(odd ? f1 : f0);
            uint32_t a3 = f2tf(odd ? f3 : f2);
            #pragma unroll
            for (int dt = 0; dt < 8; dt++) {
                uint32_t b0 = __float_as_uint(VS(kk * 8 + qd,     dt * 8 + g));
                uint32_t b1 = __float_as_uint(VS(kk * 8 + qd + 4, dt * 8 + g));
                mma_tf32(o[dt], a0, a1, a2, a3, b0, b1);
            }
        }
    }

    const float inv0 = 1.f / l0, inv1 = 1.f / l1;
    float* ob = g_attn + ((size_t)b * NN + q0 + 16 * w) * EE + h * DD;
    #pragma unroll
    for (int dt = 0; dt < 8; dt++) {
        float2 v0 = make_float2(f2tf_f(o[dt][0] * inv0), f2tf_f(o[dt][1] * inv0));
        float2 v1 = make_float2(f2tf_f(o[dt][2] * inv1), f2tf_f(o[dt][3] * inv1));
        *(float2*)(ob + (size_t)g * EE + dt * 8 + 2 * qd) = v0;
        *(float2*)(ob + (size_t)(g + 8) * EE + dt * 8 + 2 * qd) = v1;
    }
}

// ---------------------------------------------------------------------------
// Stage C: out = g_attn @ Wf^T, tf32 mma. 128x128x32, 2-stage single-barrier
// cp.async pipeline (R3 version). grid (8, 96), block 256, smem 73728 B.
// smem: As[2][128][36] | Ws[2][128][36]
// ---------------------------------------------------------------------------
#define GAS(bf, r, c_) sm[(bf) * 4608 + (r) * 36 + (c_)]
#define GWS(bf, r, c_) sm[9216 + (bf) * 4608 + (r) * 36 + (c_)]

__global__ __launch_bounds__(256, 2) void gemm_tf32_kernel(float* __restrict__ out)
{
    extern __shared__ float sm[];

    const int e0 = blockIdx.x * 128;
    const int m0 = blockIdx.y * 128;
    const int tid = threadIdx.x;
    const int w = tid >> 5;
    const int lane = tid & 31;
    const int g = lane >> 2, qd = lane & 3;
    const int mb = (w & 1) * 64;
    const int nb = (w >> 1) * 32;

    const float* Ab = g_attn + (size_t)m0 * EE;
    const float* Wb = g_wtf + (size_t)e0 * EE;

    const int rr = tid >> 3;           // 0..31
    const int c4 = (tid & 7) * 4;      // 0..28

    float acc[4][4][4] = {};

    #pragma unroll
    for (int i = 0; i < 4; i++) {
        cp16(&GAS(0, rr + 32 * i, c4), Ab + (size_t)(rr + 32 * i) * EE + c4);
        cp16(&GWS(0, rr + 32 * i, c4), Wb + (size_t)(rr + 32 * i) * EE + c4);
    }
    cp_commit();

    for (int it = 0; it < EE / 32; it++) {
        const int buf = it & 1;
        cp_wait0();
        __syncthreads();

        if (it + 1 < EE / 32) {
            const int kc = (it + 1) * 32;
            #pragma unroll
            for (int i = 0; i < 4; i++) {
                cp16(&GAS(buf ^ 1, rr + 32 * i, c4),
                     Ab + (size_t)(rr + 32 * i) * EE + kc + c4);
                cp16(&GWS(buf ^ 1, rr + 32 * i, c4),
                     Wb + (size_t)(rr + 32 * i) * EE + kc + c4);
            }
            cp_commit();
        }

        #pragma unroll
        for (int kk = 0; kk < 4; kk++) {
            uint32_t a[4][4];
            #pragma unroll
            for (int mt = 0; mt < 4; mt++) {
                const int row = mb + mt * 16 + g;
                a[mt][0] = __float_as_uint(GAS(buf, row,     kk * 8 + qd));
                a[mt][1] = __float_as_uint(GAS(buf, row + 8, kk * 8 + qd));
                a[mt][2] = __float_as_uint(GAS(buf, row,     kk * 8 + qd + 4));
                a[mt][3] = __float_as_uint(GAS(buf, row + 8, kk * 8 + qd + 4));
            }
            #pragma unroll
            for (int nt = 0; nt < 4; nt++) {
                uint32_t b0 = __float_as_uint(GWS(buf, nb + nt * 8 + g, kk * 8 + qd));
                uint32_t b1 = __float_as_uint(GWS(buf, nb + nt * 8 + g, kk * 8 + qd + 4));
                #pragma unroll
                for (int mt = 0; mt < 4; mt++)
                    mma_tf32(acc[mt][nt], a[mt][0], a[mt][1], a[mt][2], a[mt][3], b0, b1);
            }
        }
    }

    #pragma unroll
    for (int mt = 0; mt < 4; mt++) {
        const int row0 = m0 + mb + mt * 16 + g;
        #pragma unroll
        for (int nt = 0; nt < 4; nt++) {
            const int col = e0 + nb + nt * 8 + 2 * qd;
            *(float2*)(out + (size_t)row0 * EE + col) =
                make_float2(acc[mt][nt][0], acc[mt][nt][1]);
            *(float2*)(out + (size_t)(row0 + 8) * EE + col) =
                make_float2(acc[mt][nt][2], acc[mt][nt][3]);
        }
    }
}

// ---------------------------------------------------------------------------
extern "C" void kernel_launch(void* const* d_in, const int* in_sizes, int n_in,
                              void* d_out, int out_size)
{
    const float* q    = (const float*)d_in[0];
    const float* k    = (const float*)d_in[1];
    const float* v    = (const float*)d_in[2];
    const float* mask = (const float*)d_in[3];
    const float* Wq   = (const float*)d_in[4];
    const float* Wk   = (const float*)d_in[5];
    const float* Wv   = (const float*)d_in[6];
    const float* Wf   = (const float*)d_in[7];
    float* out = (float*)d_out;

    const int proj_smem = (128 * 76 + 64 * 76) * (int)sizeof(float);  // 58368
    const int attn_smem = 19968 * (int)sizeof(float);                 // 79872
    const int gemm_smem = 18432 * (int)sizeof(float);                 // 73728
    cudaFuncSetAttribute(proj_mma_kernel,
                         cudaFuncAttributeMaxDynamicSharedMemorySize, proj_smem);
    cudaFuncSetAttribute(attn_tf32_kernel,
                         cudaFuncAttributeMaxDynamicSharedMemorySize, attn_smem);
    cudaFuncSetAttribute(gemm_tf32_kernel,
                         cudaFuncAttributeMaxDynamicSharedMemorySize, gemm_smem);

    proj_mma_kernel<<<dim3(NN / 128, BB * HH, 4), 256, proj_smem>>>(
        q, k, v, Wq, Wk, Wv, Wf);
    attn_tf32_kernel<<<dim3(NN / 128, BB * HH), 256, attn_smem>>>(mask);
    gemm_tf32_kernel<<<dim3(EE / 128, (BB * NN) / 128), 256, gemm_smem>>>(out);
}